// round 10
// baseline (speedup 1.0000x reference)
#include <cuda_runtime.h>
#include <cuda_bf16.h>
#include <cstdint>

#define NTOKENS 16384
#define DDIM    1024
#define FDIM    64
#define NOUTS   192
#define TILEK   64
#define NCHUNK  16
#define MTOK    64

// smem (bytes):
//  [0,768)    biases
//  [768,800)  mbarriers: full0@768 full1@776 empty0@784 empty1@792
//  X stages:  X0@1024, X1@17408   (each 16KB: hi 8K | lo 8K; 64 rows x 128B SW128)
//  W stages:  W0@33792, W1@82944  (each 48KB: hi 24K | lo 24K; 192 rows x 128B SW128)
#define BAR_FULL0 768
#define BAR_FULL1 776
#define BAR_EMPTY0 784
#define BAR_EMPTY1 792
#define XOFF      1024
#define XSTRIDE   16384
#define XLO_REL   8192
#define WOFF      33792
#define WSTRIDE   49152
#define WLO_REL   24576
#define SMEM_BYTES (WOFF + 2 * WSTRIDE)   // 132096
#define EPI_OFF   1024
#define EPI_PITCH 193

__device__ __align__(16) __nv_bfloat16 g_Whi[NOUTS * DDIM];
__device__ __align__(16) __nv_bfloat16 g_Wlo[NOUTS * DDIM];

__device__ __forceinline__ uint32_t smem_u32(const void* p) {
    uint32_t a;
    asm("{ .reg .u64 t; cvta.to.shared.u64 t, %1; cvt.u32.u64 %0, t; }" : "=r"(a) : "l"(p));
    return a;
}
#define SW128(o) ((o) ^ (((o) >> 3) & 0x70))

#define CPASYNC16(dst, src) \
    asm volatile("cp.async.cg.shared.global [%0], [%1], 16;" :: "r"(dst), "l"(src) : "memory")
#define CP_COMMIT() asm volatile("cp.async.commit_group;" ::: "memory")
#define CP_WAIT0()  asm volatile("cp.async.wait_group 0;" ::: "memory")

#define MBAR_INIT(addr, cnt) \
    asm volatile("mbarrier.init.shared.b64 [%0], %1;" :: "r"(addr), "r"((uint32_t)(cnt)) : "memory")
#define MBAR_ARRIVE(addr) \
    asm volatile("mbarrier.arrive.shared.b64 _, [%0];" :: "r"(addr) : "memory")
#define MBAR_WAIT(mbar, par) do { \
    uint32_t _m = (uint32_t)(mbar), _p = (uint32_t)(par), _d; \
    asm volatile("{\n\t.reg .pred p;\n\t" \
        "mbarrier.try_wait.parity.acquire.cta.shared::cta.b64 p, [%1], %2;\n\t" \
        "selp.b32 %0, 1, 0, p;\n\t}" : "=r"(_d) : "r"(_m), "r"(_p) : "memory"); \
    if (!_d) { \
        asm volatile("{\n\t.reg .pred P1;\n\t" \
            "WL_%=:\n\t" \
            "mbarrier.try_wait.parity.acquire.cta.shared::cta.b64 P1, [%0], %1, 0x989680;\n\t" \
            "@P1 bra.uni WD_%=;\n\t" \
            "bra.uni WL_%=;\n\t" \
            "WD_%=:\n\t}" :: "r"(_m), "r"(_p) : "memory"); \
    } \
} while (0)

#define LDSM4(r0, r1, r2, r3, addr) \
    asm volatile("ldmatrix.sync.aligned.m8n8.x4.shared.b16 {%0,%1,%2,%3}, [%4];" \
                 : "=r"(r0), "=r"(r1), "=r"(r2), "=r"(r3) : "r"(addr))

#define MMA_BF16(C, A, B) \
    asm volatile("mma.sync.aligned.m16n8k16.row.col.f32.bf16.bf16.f32 " \
                 "{%0,%1,%2,%3}, {%4,%5,%6,%7}, {%8,%9}, {%0,%1,%2,%3};" \
                 : "+f"((C)[0]), "+f"((C)[1]), "+f"((C)[2]), "+f"((C)[3]) \
                 : "r"((A)[0]), "r"((A)[1]), "r"((A)[2]), "r"((A)[3]), \
                   "r"((B)[0]), "r"((B)[1]))

#define STS128(addr, v) \
    asm volatile("st.shared.v4.b32 [%0], {%1,%2,%3,%4};" \
                 :: "r"(addr), "r"((v).x), "r"((v).y), "r"((v).z), "r"((v).w) : "memory")

// ---------- prep: split weights to bf16 hi/lo, combined [192 n][1024 k] ----------
__global__ void prep_w(const float* __restrict__ Wt, const float* __restrict__ Wf,
                       const float* __restrict__ Wg) {
    int idx = blockIdx.x * 256 + threadIdx.x;
    int n = idx >> 10, k = idx & 1023;
    float v = (n < 64)  ? Wt[(size_t)k * FDIM + n]
            : (n < 128) ? Wf[(size_t)k * FDIM + (n - 64)]
                        : Wg[(size_t)(n - 128) * DDIM + k];
    __nv_bfloat16 h = __float2bfloat16(v);
    g_Whi[idx] = h;
    g_Wlo[idx] = __float2bfloat16(v - __bfloat162float(h));
}

// ---------- main: 8 consumer warps (MMA, M32xN48 tiles) + 2 producer warps ----------
__global__ __launch_bounds__(320, 1)
void moe_gate_main(const float* __restrict__ x,
                   const float* __restrict__ bt, const float* __restrict__ bfe,
                   const float* __restrict__ bg, const float* __restrict__ alpha,
                   float* __restrict__ out) {
    extern __shared__ char smem[];
    const uint32_t sb = smem_u32(smem);
    const int tid  = threadIdx.x;
    const int wid  = tid >> 5;
    const int lane = tid & 31;
    const int tok0 = blockIdx.x * MTOK;

    float* biass = reinterpret_cast<float*>(smem);
    if (tid < 192)
        biass[tid] = (tid < 64) ? bt[tid] : (tid < 128) ? bfe[tid - 64] : bg[tid - 128];
    if (tid == 0) {
        MBAR_INIT(sb + BAR_FULL0, 64);
        MBAR_INIT(sb + BAR_FULL1, 64);
        MBAR_INIT(sb + BAR_EMPTY0, 256);
        MBAR_INIT(sb + BAR_EMPTY1, 256);
    }
    __syncthreads();

    float acc[2][6][4];

    if (wid < 8) {
        // ================= consumers: warp tile M32 x N48 =================
        const int WT    = (wid & 1) * 32;
        const int nbase = (wid >> 1) * 48;
        const uint32_t aRow = ((lane >> 3) & 1) * 8 + (lane & 7);
        const uint32_t aK   = ((lane >> 4) & 1) * 16;
        const uint32_t bRow = ((lane >> 4) & 1) * 8 + (lane & 7);
        const uint32_t bK   = ((lane >> 3) & 1) * 16;

        #pragma unroll
        for (int i = 0; i < 2; i++)
            #pragma unroll
            for (int j = 0; j < 6; j++)
                #pragma unroll
                for (int c = 0; c < 4; c++) acc[i][j][c] = 0.f;

        for (int t = 0; t < NCHUNK; ++t) {
            const int s = t & 1;
            MBAR_WAIT(sb + (s ? BAR_FULL1 : BAR_FULL0), (t >> 1) & 1);

            const uint32_t xhi = sb + XOFF + s * XSTRIDE;
            const uint32_t xlo = xhi + XLO_REL;
            const uint32_t whi = sb + WOFF + s * WSTRIDE;
            const uint32_t wlo = whi + WLO_REL;

            #pragma unroll
            for (int ks = 0; ks < 4; ++ks) {
                uint32_t Ahi[2][4], Alo[2][4], Bhi[6][2], Blo[6][2];
                #pragma unroll
                for (int mt = 0; mt < 2; mt++) {
                    uint32_t off = SW128((uint32_t)((WT + mt * 16 + aRow) * 128 + ks * 32 + aK));
                    LDSM4(Ahi[mt][0], Ahi[mt][1], Ahi[mt][2], Ahi[mt][3], xhi + off);
                    LDSM4(Alo[mt][0], Alo[mt][1], Alo[mt][2], Alo[mt][3], xlo + off);
                }
                #pragma unroll
                for (int bp = 0; bp < 3; bp++) {
                    uint32_t off = SW128((uint32_t)((nbase + bp * 16 + bRow) * 128 + ks * 32 + bK));
                    LDSM4(Bhi[2 * bp][0], Bhi[2 * bp][1], Bhi[2 * bp + 1][0], Bhi[2 * bp + 1][1],
                          whi + off);
                    LDSM4(Blo[2 * bp][0], Blo[2 * bp][1], Blo[2 * bp + 1][0], Blo[2 * bp + 1][1],
                          wlo + off);
                }
                // pass-outermost (12-MMA reuse distance per accumulator)
                #pragma unroll
                for (int mt = 0; mt < 2; mt++)
                    #pragma unroll
                    for (int nt = 0; nt < 6; nt++)
                        MMA_BF16(acc[mt][nt], Ahi[mt], Bhi[nt]);
                #pragma unroll
                for (int mt = 0; mt < 2; mt++)
                    #pragma unroll
                    for (int nt = 0; nt < 6; nt++)
                        MMA_BF16(acc[mt][nt], Alo[mt], Bhi[nt]);
                #pragma unroll
                for (int mt = 0; mt < 2; mt++)
                    #pragma unroll
                    for (int nt = 0; nt < 6; nt++)
                        MMA_BF16(acc[mt][nt], Ahi[mt], Blo[nt]);
            }
            MBAR_ARRIVE(sb + (s ? BAR_EMPTY1 : BAR_EMPTY0));
        }
    } else {
        // ================= producers (2 warps, 64 threads) =================
        const int ptid = tid - 256;
        const char* hb = reinterpret_cast<const char*>(g_Whi);
        const char* lb = reinterpret_cast<const char*>(g_Wlo);

        for (int t = 0; t < NCHUNK; ++t) {
            const int s = t & 1;
            if (t >= 2) MBAR_WAIT(sb + (s ? BAR_EMPTY1 : BAR_EMPTY0), ((t - 2) >> 1) & 1);

            // W chunk via cp.async (issued first, overlaps x convert below)
            const uint32_t wdst = sb + WOFF + s * WSTRIDE;
            #pragma unroll
            for (int j = 0; j < 24; j++) {
                int idx = ptid + 64 * j;                 // [0,1536)
                int nrow = idx >> 3, c = idx & 7;
                size_t go = (size_t)nrow * 2048 + (size_t)t * 128 + c * 16;
                uint32_t off = SW128((uint32_t)(nrow * 128 + c * 16));
                CPASYNC16(wdst + off,           hb + go);
                CPASYNC16(wdst + WLO_REL + off, lb + go);
            }
            CP_COMMIT();

            // x chunk (64 rows): ldg fp32 -> hi/lo bf16 -> smem (SW128)
            const uint32_t xb = sb + XOFF + s * XSTRIDE;
            #pragma unroll
            for (int j = 0; j < 8; j++) {
                int q = ptid + 64 * j;                   // [0,512) groups of 8 floats
                int row = q >> 3, oc = q & 7;
                const float4* p = reinterpret_cast<const float4*>(
                    x + (size_t)(tok0 + row) * DDIM + t * TILEK + oc * 8);
                float4 f0 = p[0], f1 = p[1];
                const float fp[8] = {f0.x, f0.y, f0.z, f0.w, f1.x, f1.y, f1.z, f1.w};
                uint4 hv, lv;
                uint32_t* hw = reinterpret_cast<uint32_t*>(&hv);
                uint32_t* lw = reinterpret_cast<uint32_t*>(&lv);
                #pragma unroll
                for (int e = 0; e < 4; e++) {
                    float a = fp[2 * e], b = fp[2 * e + 1];
                    __nv_bfloat16 ah = __float2bfloat16(a), bh = __float2bfloat16(b);
                    float al = a - __bfloat162float(ah);
                    float bl = b - __bfloat162float(bh);
                    __nv_bfloat162 hp = __halves2bfloat162(ah, bh);
                    __nv_bfloat162 lp = __floats2bfloat162_rn(al, bl);
                    hw[e] = *reinterpret_cast<uint32_t*>(&hp);
                    lw[e] = *reinterpret_cast<uint32_t*>(&lp);
                }
                uint32_t off = SW128((uint32_t)(row * 128 + oc * 16));
                STS128(xb + off,           hv);
                STS128(xb + XLO_REL + off, lv);
            }
            CP_WAIT0();
            MBAR_ARRIVE(sb + (s ? BAR_FULL1 : BAR_FULL0));
        }
    }

    __syncthreads();   // pipeline done; smem free for epilogue

    // ---------------- epilogue ----------------
    float* epi = reinterpret_cast<float*>(smem + EPI_OFF);
    if (wid < 8) {
        const int WT    = (wid & 1) * 32;
        const int nbase = (wid >> 1) * 48;
        const int rg  = lane >> 2;
        const int cp2 = (lane & 3) * 2;
        #pragma unroll
        for (int mt = 0; mt < 2; mt++)
            #pragma unroll
            for (int nt = 0; nt < 6; nt++) {
                int r0 = WT + mt * 16 + rg;
                int c0 = nbase + nt * 8 + cp2;
                epi[r0 * EPI_PITCH + c0]           = acc[mt][nt][0];
                epi[r0 * EPI_PITCH + c0 + 1]       = acc[mt][nt][1];
                epi[(r0 + 8) * EPI_PITCH + c0]     = acc[mt][nt][2];
                epi[(r0 + 8) * EPI_PITCH + c0 + 1] = acc[mt][nt][3];
            }
    }
    __syncthreads();

    if (tid < MTOK) {
        const float* row = epi + tid * EPI_PITCH;
        const float asig = 1.f / (1.f + __expf(-alpha[0]));
        float v[64], g[64];

        #pragma unroll
        for (int i = 0; i < 64; i++)
            g[i] = 1.f / (1.f + __expf(-(row[128 + i] + biass[128 + i])));
        #pragma unroll
        for (int i = 0; i < 64; i++) v[i] = row[i] + biass[i];

        float m0 = v[0];
        #pragma unroll
        for (int i = 1; i < 64; i++) m0 = fmaxf(m0, v[i]);
        float prev = m0;
        for (int it = 0; it < 7; ++it) {
            float m = -3.4e38f;
            #pragma unroll
            for (int i = 0; i < 64; i++) {
                float c = (v[i] < prev) ? v[i] : -3.4e38f;
                m = fmaxf(m, c);
            }
            prev = m;
        }
        float tn = 0.f, td = 0.f;
        #pragma unroll
        for (int i = 0; i < 64; i++) {
            if (v[i] >= prev) {
                float e = __expf(v[i] - m0);
                tn += e * g[i]; td += e;
            }
        }

        #pragma unroll
        for (int i = 0; i < 64; i++) v[i] = row[64 + i] + biass[64 + i];
        float mf = v[0];
        #pragma unroll
        for (int i = 1; i < 64; i++) mf = fmaxf(mf, v[i]);
        float fn = 0.f, fd = 0.f;
        #pragma unroll
        for (int i = 0; i < 64; i++) {
            float e = __expf(v[i] - mf);
            fn += e * g[i]; fd += e;
        }

        out[tok0 + tid] = asig * (tn / td) + (1.f - asig) * (fn / fd);
    }
}

extern "C" void kernel_launch(void* const* d_in, const int* in_sizes, int n_in,
                              void* d_out, int out_size) {
    const float* x  = (const float*)d_in[0];
    const float* Wt = (const float*)d_in[1];
    const float* bt = (const float*)d_in[2];
    const float* Wf = (const float*)d_in[3];
    const float* bf = (const float*)d_in[4];
    const float* Wg = (const float*)d_in[5];
    const float* bg = (const float*)d_in[6];
    const float* al = (const float*)d_in[7];
    float* out = (float*)d_out;

    cudaFuncSetAttribute(moe_gate_main,
                         cudaFuncAttributeMaxDynamicSharedMemorySize, SMEM_BYTES);
    prep_w<<<NOUTS * DDIM / 256, 256>>>(Wt, Wf, Wg);
    moe_gate_main<<<NTOKENS / MTOK, 320, SMEM_BYTES>>>(x, bt, bf, bg, al, out);
}

// round 11
// speedup vs baseline: 1.2204x; 1.2204x over previous
#include <cuda_runtime.h>
#include <cuda_bf16.h>
#include <cstdint>

#define NTOKENS 16384
#define DDIM    1024
#define FDIM    64
#define NOUTS   192
#define TILEK   64
#define NCHUNK  16
#define MTOK    128

// smem (bytes):
//  [0,768)    biases
//  [768,800)  mbarriers: full0@768 full1@776 empty0@784 empty1@792
//  X stages:  X0@1024, X1@33792   (each: hi 16K | lo 16K)
//  W stages:  W0@66560, W1@115712 (each: hi 24K | lo 24K)
#define BAR_FULL0 768
#define BAR_FULL1 776
#define BAR_EMPTY0 784
#define BAR_EMPTY1 792
#define XOFF      1024
#define XSTRIDE   32768
#define XLO_REL   16384
#define WOFF      66560
#define WSTRIDE   49152
#define WLO_REL   24576
#define SMEM_BYTES (WOFF + 2 * WSTRIDE)   // 164864
#define EPI_OFF   1024
#define EPI_PITCH 193

__device__ __align__(16) __nv_bfloat16 g_Whi[NOUTS * DDIM];
__device__ __align__(16) __nv_bfloat16 g_Wlo[NOUTS * DDIM];

__device__ __forceinline__ uint32_t smem_u32(const void* p) {
    uint32_t a;
    asm("{ .reg .u64 t; cvta.to.shared.u64 t, %1; cvt.u32.u64 %0, t; }" : "=r"(a) : "l"(p));
    return a;
}
#define SW128(o) ((o) ^ (((o) >> 3) & 0x70))

#define CPASYNC16(dst, src) \
    asm volatile("cp.async.cg.shared.global [%0], [%1], 16;" :: "r"(dst), "l"(src) : "memory")
#define CP_COMMIT() asm volatile("cp.async.commit_group;" ::: "memory")
#define CP_WAIT0()  asm volatile("cp.async.wait_group 0;" ::: "memory")

#define MBAR_INIT(addr, cnt) \
    asm volatile("mbarrier.init.shared.b64 [%0], %1;" :: "r"(addr), "r"((uint32_t)(cnt)) : "memory")
#define MBAR_ARRIVE(addr) \
    asm volatile("mbarrier.arrive.shared.b64 _, [%0];" :: "r"(addr) : "memory")
#define MBAR_WAIT(mbar, par) do { \
    uint32_t _m = (uint32_t)(mbar), _p = (uint32_t)(par), _d; \
    asm volatile("{\n\t.reg .pred p;\n\t" \
        "mbarrier.try_wait.parity.acquire.cta.shared::cta.b64 p, [%1], %2;\n\t" \
        "selp.b32 %0, 1, 0, p;\n\t}" : "=r"(_d) : "r"(_m), "r"(_p) : "memory"); \
    if (!_d) { \
        asm volatile("{\n\t.reg .pred P1;\n\t" \
            "WL_%=:\n\t" \
            "mbarrier.try_wait.parity.acquire.cta.shared::cta.b64 P1, [%0], %1, 0x989680;\n\t" \
            "@P1 bra.uni WD_%=;\n\t" \
            "bra.uni WL_%=;\n\t" \
            "WD_%=:\n\t}" :: "r"(_m), "r"(_p) : "memory"); \
    } \
} while (0)

#define LDSM4(r0, r1, r2, r3, addr) \
    asm volatile("ldmatrix.sync.aligned.m8n8.x4.shared.b16 {%0,%1,%2,%3}, [%4];" \
                 : "=r"(r0), "=r"(r1), "=r"(r2), "=r"(r3) : "r"(addr))

#define MMA_BF16(C, A, B) \
    asm volatile("mma.sync.aligned.m16n8k16.row.col.f32.bf16.bf16.f32 " \
                 "{%0,%1,%2,%3}, {%4,%5,%6,%7}, {%8,%9}, {%0,%1,%2,%3};" \
                 : "+f"((C)[0]), "+f"((C)[1]), "+f"((C)[2]), "+f"((C)[3]) \
                 : "r"((A)[0]), "r"((A)[1]), "r"((A)[2]), "r"((A)[3]), \
                   "r"((B)[0]), "r"((B)[1]))

#define STS128(addr, v) \
    asm volatile("st.shared.v4.b32 [%0], {%1,%2,%3,%4};" \
                 :: "r"(addr), "r"((v).x), "r"((v).y), "r"((v).z), "r"((v).w) : "memory")

// ---------- prep: split weights to bf16 hi/lo, combined [192 n][1024 k] ----------
__global__ void prep_w(const float* __restrict__ Wt, const float* __restrict__ Wf,
                       const float* __restrict__ Wg) {
    int idx = blockIdx.x * 256 + threadIdx.x;
    int n = idx >> 10, k = idx & 1023;
    float v = (n < 64)  ? Wt[(size_t)k * FDIM + n]
            : (n < 128) ? Wf[(size_t)k * FDIM + (n - 64)]
                        : Wg[(size_t)(n - 128) * DDIM + k];
    __nv_bfloat16 h = __float2bfloat16(v);
    g_Whi[idx] = h;
    g_Wlo[idx] = __float2bfloat16(v - __bfloat162float(h));
}

// ---------- main: 8 consumer warps (MMA) + 2 producer warps (X/W feed) ----------
__global__ __launch_bounds__(320, 1)
void moe_gate_main(const float* __restrict__ x,
                   const float* __restrict__ bt, const float* __restrict__ bfe,
                   const float* __restrict__ bg, const float* __restrict__ alpha,
                   float* __restrict__ out) {
    extern __shared__ char smem[];
    const uint32_t sb = smem_u32(smem);
    const int tid  = threadIdx.x;
    const int wid  = tid >> 5;
    const int lane = tid & 31;
    const int tok0 = blockIdx.x * MTOK;

    float* biass = reinterpret_cast<float*>(smem);
    if (tid < 192)
        biass[tid] = (tid < 64) ? bt[tid] : (tid < 128) ? bfe[tid - 64] : bg[tid - 128];
    if (tid == 0) {
        MBAR_INIT(sb + BAR_FULL0, 64);
        MBAR_INIT(sb + BAR_FULL1, 64);
        MBAR_INIT(sb + BAR_EMPTY0, 256);
        MBAR_INIT(sb + BAR_EMPTY1, 256);
    }
    __syncthreads();

    float acc[4][6][4];

    if (wid < 8) {
        // ================= consumers =================
        const int WT    = (wid & 1) * 64;
        const int nbase = (wid >> 1) * 48;
        // SMSP partner warps (wid, wid+4) get k-step phase offset 2 so their
        // LDSM bursts interleave with the partner's MMA runs (tensor pipe stays fed)
        const int ksoff = (wid >> 2) << 1;
        const uint32_t aRow = ((lane >> 3) & 1) * 8 + (lane & 7);
        const uint32_t aK   = ((lane >> 4) & 1) * 16;
        const uint32_t bRow = ((lane >> 4) & 1) * 8 + (lane & 7);
        const uint32_t bK   = ((lane >> 3) & 1) * 16;

        #pragma unroll
        for (int i = 0; i < 4; i++)
            #pragma unroll
            for (int j = 0; j < 6; j++)
                #pragma unroll
                for (int c = 0; c < 4; c++) acc[i][j][c] = 0.f;

        for (int t = 0; t < NCHUNK; ++t) {
            const int s = t & 1;
            MBAR_WAIT(sb + (s ? BAR_FULL1 : BAR_FULL0), (t >> 1) & 1);

            const uint32_t xhi = sb + XOFF + s * XSTRIDE;
            const uint32_t xlo = xhi + XLO_REL;
            const uint32_t whi = sb + WOFF + s * WSTRIDE;
            const uint32_t wlo = whi + WLO_REL;

            #pragma unroll
            for (int kk = 0; kk < 4; ++kk) {
                const int ks = (kk + ksoff) & 3;
                uint32_t Ahi[4][4], Alo[4][4], Bhi[6][2], Blo[6][2];
                #pragma unroll
                for (int mt = 0; mt < 4; mt++) {
                    uint32_t off = SW128((uint32_t)((WT + mt * 16 + aRow) * 128 + ks * 32 + aK));
                    LDSM4(Ahi[mt][0], Ahi[mt][1], Ahi[mt][2], Ahi[mt][3], xhi + off);
                    LDSM4(Alo[mt][0], Alo[mt][1], Alo[mt][2], Alo[mt][3], xlo + off);
                }
                #pragma unroll
                for (int bp = 0; bp < 3; bp++) {
                    uint32_t off = SW128((uint32_t)((nbase + bp * 16 + bRow) * 128 + ks * 32 + bK));
                    LDSM4(Bhi[2 * bp][0], Bhi[2 * bp][1], Bhi[2 * bp + 1][0], Bhi[2 * bp + 1][1],
                          whi + off);
                    LDSM4(Blo[2 * bp][0], Blo[2 * bp][1], Blo[2 * bp + 1][0], Blo[2 * bp + 1][1],
                          wlo + off);
                }
                // pass-outermost: same-acc reuse distance = 24 MMAs
                #pragma unroll
                for (int mt = 0; mt < 4; mt++)
                    #pragma unroll
                    for (int nt = 0; nt < 6; nt++)
                        MMA_BF16(acc[mt][nt], Ahi[mt], Bhi[nt]);
                #pragma unroll
                for (int mt = 0; mt < 4; mt++)
                    #pragma unroll
                    for (int nt = 0; nt < 6; nt++)
                        MMA_BF16(acc[mt][nt], Alo[mt], Bhi[nt]);
                #pragma unroll
                for (int mt = 0; mt < 4; mt++)
                    #pragma unroll
                    for (int nt = 0; nt < 6; nt++)
                        MMA_BF16(acc[mt][nt], Ahi[mt], Blo[nt]);
            }
            MBAR_ARRIVE(sb + (s ? BAR_EMPTY1 : BAR_EMPTY0));
        }
    } else {
        // ================= producers (2 warps, 64 threads) =================
        const int ptid = tid - 256;
        const char* hb = reinterpret_cast<const char*>(g_Whi);
        const char* lb = reinterpret_cast<const char*>(g_Wlo);

        for (int t = 0; t < NCHUNK; ++t) {
            const int s = t & 1;
            if (t >= 2) MBAR_WAIT(sb + (s ? BAR_EMPTY1 : BAR_EMPTY0), ((t - 2) >> 1) & 1);

            const uint32_t wdst = sb + WOFF + s * WSTRIDE;
            #pragma unroll
            for (int j = 0; j < 24; j++) {
                int idx = ptid + 64 * j;                 // [0,1536)
                int nrow = idx >> 3, c = idx & 7;
                size_t go = (size_t)nrow * 2048 + (size_t)t * 128 + c * 16;
                uint32_t off = SW128((uint32_t)(nrow * 128 + c * 16));
                CPASYNC16(wdst + off,           hb + go);
                CPASYNC16(wdst + WLO_REL + off, lb + go);
            }
            CP_COMMIT();

            const uint32_t xb = sb + XOFF + s * XSTRIDE;
            #pragma unroll
            for (int j = 0; j < 16; j++) {
                int q = ptid + 64 * j;                   // [0,1024) groups of 8 floats
                int row = q >> 3, oc = q & 7;
                const float4* p = reinterpret_cast<const float4*>(
                    x + (size_t)(tok0 + row) * DDIM + t * TILEK + oc * 8);
                float4 f0 = p[0], f1 = p[1];
                const float fp[8] = {f0.x, f0.y, f0.z, f0.w, f1.x, f1.y, f1.z, f1.w};
                uint4 hv, lv;
                uint32_t* hw = reinterpret_cast<uint32_t*>(&hv);
                uint32_t* lw = reinterpret_cast<uint32_t*>(&lv);
                #pragma unroll
                for (int e = 0; e < 4; e++) {
                    float a = fp[2 * e], b = fp[2 * e + 1];
                    __nv_bfloat16 ah = __float2bfloat16(a), bh = __float2bfloat16(b);
                    float al = a - __bfloat162float(ah);
                    float bl = b - __bfloat162float(bh);
                    __nv_bfloat162 hp = __halves2bfloat162(ah, bh);
                    __nv_bfloat162 lp = __floats2bfloat162_rn(al, bl);
                    hw[e] = *reinterpret_cast<uint32_t*>(&hp);
                    lw[e] = *reinterpret_cast<uint32_t*>(&lp);
                }
                uint32_t off = SW128((uint32_t)(row * 128 + oc * 16));
                STS128(xb + off,           hv);
                STS128(xb + XLO_REL + off, lv);
            }
            CP_WAIT0();
            MBAR_ARRIVE(sb + (s ? BAR_FULL1 : BAR_FULL0));
        }
    }

    __syncthreads();   // pipeline done; smem free for epilogue

    // ---------------- epilogue ----------------
    float* epi = reinterpret_cast<float*>(smem + EPI_OFF);
    if (wid < 8) {
        const int WT    = (wid & 1) * 64;
        const int nbase = (wid >> 1) * 48;
        const int rg  = lane >> 2;
        const int cp2 = (lane & 3) * 2;
        #pragma unroll
        for (int mt = 0; mt < 4; mt++)
            #pragma unroll
            for (int nt = 0; nt < 6; nt++) {
                int r0 = WT + mt * 16 + rg;
                int c0 = nbase + nt * 8 + cp2;
                epi[r0 * EPI_PITCH + c0]           = acc[mt][nt][0];
                epi[r0 * EPI_PITCH + c0 + 1]       = acc[mt][nt][1];
                epi[(r0 + 8) * EPI_PITCH + c0]     = acc[mt][nt][2];
                epi[(r0 + 8) * EPI_PITCH + c0 + 1] = acc[mt][nt][3];
            }
    }
    __syncthreads();

    if (tid < MTOK) {
        const float* row = epi + tid * EPI_PITCH;
        const float asig = 1.f / (1.f + __expf(-alpha[0]));
        float v[64], g[64];

        #pragma unroll
        for (int i = 0; i < 64; i++)
            g[i] = 1.f / (1.f + __expf(-(row[128 + i] + biass[128 + i])));
        #pragma unroll
        for (int i = 0; i < 64; i++) v[i] = row[i] + biass[i];

        float m0 = v[0];
        #pragma unroll
        for (int i = 1; i < 64; i++) m0 = fmaxf(m0, v[i]);
        float prev = m0;
        for (int it = 0; it < 7; ++it) {
            float m = -3.4e38f;
            #pragma unroll
            for (int i = 0; i < 64; i++) {
                float c = (v[i] < prev) ? v[i] : -3.4e38f;
                m = fmaxf(m, c);
            }
            prev = m;
        }
        float tn = 0.f, td = 0.f;
        #pragma unroll
        for (int i = 0; i < 64; i++) {
            if (v[i] >= prev) {
                float e = __expf(v[i] - m0);
                tn += e * g[i]; td += e;
            }
        }

        #pragma unroll
        for (int i = 0; i < 64; i++) v[i] = row[64 + i] + biass[64 + i];
        float mf = v[0];
        #pragma unroll
        for (int i = 1; i < 64; i++) mf = fmaxf(mf, v[i]);
        float fn = 0.f, fd = 0.f;
        #pragma unroll
        for (int i = 0; i < 64; i++) {
            float e = __expf(v[i] - mf);
            fn += e * g[i]; fd += e;
        }

        out[tok0 + tid] = asig * (tn / td) + (1.f - asig) * (fn / fd);
    }
}

extern "C" void kernel_launch(void* const* d_in, const int* in_sizes, int n_in,
                              void* d_out, int out_size) {
    const float* x  = (const float*)d_in[0];
    const float* Wt = (const float*)d_in[1];
    const float* bt = (const float*)d_in[2];
    const float* Wf = (const float*)d_in[3];
    const float* bf = (const float*)d_in[4];
    const float* Wg = (const float*)d_in[5];
    const float* bg = (const float*)d_in[6];
    const float* al = (const float*)d_in[7];
    float* out = (float*)d_out;

    cudaFuncSetAttribute(moe_gate_main,
                         cudaFuncAttributeMaxDynamicSharedMemorySize, SMEM_BYTES);
    prep_w<<<NOUTS * DDIM / 256, 256>>>(Wt, Wf, Wg);
    moe_gate_main<<<NTOKENS / MTOK, 320, SMEM_BYTES>>>(x, bt, bf, bg, al, out);
}